// round 8
// baseline (speedup 1.0000x reference)
#include <cuda_runtime.h>
#include <math.h>

#define B_   4096
#define D_   1024
#define F_   24576
#define K1   32      /* TOPK */
#define K2_  256     /* DEAD_TOPK */
#define DEAD_CUT 100000
#define NTH  512     /* threads in row kernel */

// ---------------------------------------------------------------------------
// Scratch (device globals: no cudaMalloc allowed)
// ---------------------------------------------------------------------------
__device__ float  g_project[(size_t)B_ * (size_t)F_];   // 402 MB
__device__ double g_sum;
__device__ double g_sumsq;

__global__ void zero_stats_kernel() {
    g_sum = 0.0;
    g_sumsq = 0.0;
}

// ---------------------------------------------------------------------------
// SGEMM: project[b,f] = sum_d (embed[b,d]-bias[d]) * W[f,d]
// 128x128 tile, BK=16, 256 threads, 8x8 micro-tile, double buffered.
// Two-level accumulation (per-tile partial -> main acc) to cut rounding error
// from ~8e-7 to ~2.8e-7: the dead-topk boundary flips scale linearly with it.
// Also accumulates global sum / sumsq of project for std().
// ---------------------------------------------------------------------------
#define BM 128
#define BN 128
#define BK 16

__global__ __launch_bounds__(256, 1)
void gemm_kernel(const float* __restrict__ embed,
                 const float* __restrict__ bias,
                 const float* __restrict__ W)
{
    __shared__ __align__(16) float As[2][BK][BM];
    __shared__ __align__(16) float Bs[2][BK][BN];

    const int tid  = threadIdx.x;
    const int row0 = blockIdx.y * BM;   // batch rows
    const int col0 = blockIdx.x * BN;   // feature cols

    // loader mapping: each thread loads 2 float4 for A and 2 for B per stage
    const int ar0 = tid >> 2;                 // rows 0..63
    const int ar1 = (tid + 256) >> 2;         // rows 64..127
    const int aq  = tid & 3;                  // which float4 of the 16-wide k slab

    const float* Ap0 = embed + (size_t)(row0 + ar0) * D_ + aq * 4;
    const float* Ap1 = embed + (size_t)(row0 + ar1) * D_ + aq * 4;
    const float* Bp0 = W     + (size_t)(col0 + ar0) * D_ + aq * 4;
    const float* Bp1 = W     + (size_t)(col0 + ar1) * D_ + aq * 4;

    float acc[8][8];
#pragma unroll
    for (int i = 0; i < 8; i++)
#pragma unroll
        for (int j = 0; j < 8; j++) acc[i][j] = 0.0f;

    float4 a0, a1, b0, b1, bb;

    // preload tile 0
    a0 = *(const float4*)(Ap0);
    a1 = *(const float4*)(Ap1);
    b0 = *(const float4*)(Bp0);
    b1 = *(const float4*)(Bp1);
    bb = *(const float4*)(bias + aq * 4);

    int buf = 0;
    {
        const int kc = aq * 4;
        As[0][kc+0][ar0] = a0.x - bb.x;  As[0][kc+1][ar0] = a0.y - bb.y;
        As[0][kc+2][ar0] = a0.z - bb.z;  As[0][kc+3][ar0] = a0.w - bb.w;
        As[0][kc+0][ar1] = a1.x - bb.x;  As[0][kc+1][ar1] = a1.y - bb.y;
        As[0][kc+2][ar1] = a1.z - bb.z;  As[0][kc+3][ar1] = a1.w - bb.w;
        Bs[0][kc+0][ar0] = b0.x;  Bs[0][kc+1][ar0] = b0.y;
        Bs[0][kc+2][ar0] = b0.z;  Bs[0][kc+3][ar0] = b0.w;
        Bs[0][kc+0][ar1] = b1.x;  Bs[0][kc+1][ar1] = b1.y;
        Bs[0][kc+2][ar1] = b1.z;  Bs[0][kc+3][ar1] = b1.w;
    }
    __syncthreads();

    const int ty = tid >> 4;   // 0..15
    const int tx = tid & 15;   // 0..15
    const int NT = D_ / BK;    // 64

    for (int t = 0; t < NT; t++) {
        if (t + 1 < NT) {
            const int k0 = (t + 1) * BK;
            a0 = *(const float4*)(Ap0 + k0);
            a1 = *(const float4*)(Ap1 + k0);
            b0 = *(const float4*)(Bp0 + k0);
            b1 = *(const float4*)(Bp1 + k0);
            bb = *(const float4*)(bias + k0 + aq * 4);
        }
        // per-tile partial sums (fresh registers -> short rounding chains)
        float ts[8][8];
#pragma unroll
        for (int i = 0; i < 8; i++)
#pragma unroll
            for (int j = 0; j < 8; j++) ts[i][j] = 0.0f;
#pragma unroll
        for (int kk = 0; kk < BK; kk++) {
            float af[8], bf[8];
            *(float4*)&af[0] = *(const float4*)&As[buf][kk][ty * 8];
            *(float4*)&af[4] = *(const float4*)&As[buf][kk][ty * 8 + 4];
            *(float4*)&bf[0] = *(const float4*)&Bs[buf][kk][tx * 8];
            *(float4*)&bf[4] = *(const float4*)&Bs[buf][kk][tx * 8 + 4];
#pragma unroll
            for (int i = 0; i < 8; i++)
#pragma unroll
                for (int j = 0; j < 8; j++)
                    ts[i][j] += af[i] * bf[j];
        }
#pragma unroll
        for (int i = 0; i < 8; i++)
#pragma unroll
            for (int j = 0; j < 8; j++)
                acc[i][j] += ts[i][j];

        if (t + 1 < NT) {
            const int nb = buf ^ 1;
            const int kc = aq * 4;
            As[nb][kc+0][ar0] = a0.x - bb.x;  As[nb][kc+1][ar0] = a0.y - bb.y;
            As[nb][kc+2][ar0] = a0.z - bb.z;  As[nb][kc+3][ar0] = a0.w - bb.w;
            As[nb][kc+0][ar1] = a1.x - bb.x;  As[nb][kc+1][ar1] = a1.y - bb.y;
            As[nb][kc+2][ar1] = a1.z - bb.z;  As[nb][kc+3][ar1] = a1.w - bb.w;
            Bs[nb][kc+0][ar0] = b0.x;  Bs[nb][kc+1][ar0] = b0.y;
            Bs[nb][kc+2][ar0] = b0.z;  Bs[nb][kc+3][ar0] = b0.w;
            Bs[nb][kc+0][ar1] = b1.x;  Bs[nb][kc+1][ar1] = b1.y;
            Bs[nb][kc+2][ar1] = b1.z;  Bs[nb][kc+3][ar1] = b1.w;
            __syncthreads();
            buf = nb;
        }
    }

    // write C + accumulate stats
    float s = 0.0f, ss = 0.0f;
#pragma unroll
    for (int i = 0; i < 8; i++) {
        const size_t base = (size_t)(row0 + ty * 8 + i) * F_ + (col0 + tx * 8);
        float4 c0 = make_float4(acc[i][0], acc[i][1], acc[i][2], acc[i][3]);
        float4 c1 = make_float4(acc[i][4], acc[i][5], acc[i][6], acc[i][7]);
        *(float4*)&g_project[base]     = c0;
        *(float4*)&g_project[base + 4] = c1;
#pragma unroll
        for (int j = 0; j < 8; j++) { float v = acc[i][j]; s += v; ss += v * v; }
    }
#pragma unroll
    for (int o = 16; o > 0; o >>= 1) {
        s  += __shfl_down_sync(0xffffffffu, s,  o);
        ss += __shfl_down_sync(0xffffffffu, ss, o);
    }
    __shared__ double wsum[8], wss[8];
    const int w = tid >> 5, l = tid & 31;
    if (l == 0) { wsum[w] = (double)s; wss[w] = (double)ss; }
    __syncthreads();
    if (tid == 0) {
        double S = 0.0, SS = 0.0;
        for (int i = 0; i < 8; i++) { S += wsum[i]; SS += wss[i]; }
        atomicAdd(&g_sum, S);
        atomicAdd(&g_sumsq, SS);
    }
}

// ---------------------------------------------------------------------------
// Per-row top-k (exact radix select on monotone float keys) + reconstruction
// ---------------------------------------------------------------------------
__device__ __forceinline__ unsigned fkey(float v) {
    unsigned u = __float_as_uint(v);
    return (u & 0x80000000u) ? ~u : (u | 0x80000000u);
}

struct SelShared { int T; int nsel; int neq; };

__device__ void suffix_scan(unsigned* h, int NB) {
    const int tid = threadIdx.x;
    for (int off = 1; off < NB; off <<= 1) {
        unsigned v[8];
        int c = 0;
        for (int idx = tid; idx < NB; idx += NTH) {
            const int srcIdx = idx + off;
            v[c++] = (srcIdx < NB) ? h[srcIdx] : 0u;
        }
        __syncthreads();
        c = 0;
        for (int idx = tid; idx < NB; idx += NTH) h[idx] += v[c++];
        __syncthreads();
    }
}

__device__ int find_T(unsigned* h, int NB, unsigned K, int* sT) {
    const int tid = threadIdx.x;
    for (int idx = tid; idx < NB; idx += NTH)
        if (h[idx] >= K && (idx == NB - 1 || h[idx + 1] < K)) *sT = idx;
    __syncthreads();
    return *sT;
}

// exact top-K of keys sk[0..F_) -> indices in selIdx[0..K)
__device__ void select_topk(const unsigned* sk, unsigned* hist,
                            int* selIdx, int* eqIdx, int K, SelShared* sh)
{
    const int tid = threadIdx.x;
    const unsigned Ku = (unsigned)K;

    // round 1: key bits [31:20]
    for (int i = tid; i < 4096; i += NTH) hist[i] = 0u;
    __syncthreads();
    for (int i = tid; i < F_; i += NTH) atomicAdd(&hist[sk[i] >> 20], 1u);
    __syncthreads();
    suffix_scan(hist, 4096);
    const int T1 = find_T(hist, 4096, Ku, &sh->T);
    const unsigned nA1 = (T1 < 4095) ? hist[T1 + 1] : 0u;
    unsigned Kr = Ku - nA1;
    __syncthreads();

    // round 2: bits [19:8], restricted to top12 == T1
    for (int i = tid; i < 4096; i += NTH) hist[i] = 0u;
    __syncthreads();
    for (int i = tid; i < F_; i += NTH) {
        const unsigned k = sk[i];
        if ((int)(k >> 20) == T1) atomicAdd(&hist[(k >> 8) & 0xFFFu], 1u);
    }
    __syncthreads();
    suffix_scan(hist, 4096);
    const int T2 = find_T(hist, 4096, Kr, &sh->T);
    const unsigned nA2 = (T2 < 4095) ? hist[T2 + 1] : 0u;
    Kr -= nA2;
    __syncthreads();

    // round 3: bits [7:0], restricted to top24 == (T1<<12)|T2
    const unsigned pre24 = ((unsigned)T1 << 12) | (unsigned)T2;
    for (int i = tid; i < 256; i += NTH) hist[i] = 0u;
    __syncthreads();
    for (int i = tid; i < F_; i += NTH) {
        const unsigned k = sk[i];
        if ((k >> 8) == pre24) atomicAdd(&hist[k & 0xFFu], 1u);
    }
    __syncthreads();
    suffix_scan(hist, 256);
    const int T3 = find_T(hist, 256, Kr, &sh->T);
    const unsigned nA3 = (T3 < 255) ? hist[T3 + 1] : 0u;
    const int needEq = (int)(Kr - nA3);
    const unsigned kth = (pre24 << 8) | (unsigned)T3;
    __syncthreads();

    // collect: all keys > kth, plus needEq keys == kth (lowest index first)
    if (tid == 0) { sh->nsel = 0; sh->neq = 0; }
    __syncthreads();
    for (int i = tid; i < F_; i += NTH) {
        const unsigned k = sk[i];
        if (k > kth) {
            const int p = atomicAdd(&sh->nsel, 1);
            selIdx[p] = i;
        } else if (k == kth) {
            const int p = atomicAdd(&sh->neq, 1);
            if (p < 64) eqIdx[p] = i;
        }
    }
    __syncthreads();
    if (tid == 0) {
        int m = sh->neq; if (m > 64) m = 64;
        for (int a = 1; a < m; a++) {           // tiny insertion sort by index
            int v = eqIdx[a]; int c = a - 1;
            while (c >= 0 && eqIdx[c] > v) { eqIdx[c + 1] = eqIdx[c]; c--; }
            eqIdx[c + 1] = v;
        }
        const int base = sh->nsel;
        for (int a = 0; a < needEq; a++)
            selIdx[base + a] = (a < m) ? eqIdx[a] : eqIdx[0];
    }
    __syncthreads();
}

__global__ __launch_bounds__(NTH)
void row_kernel(const float* __restrict__ noise,
                const int*   __restrict__ last_usage,
                const float* __restrict__ lookup,
                const float* __restrict__ bias,
                float* __restrict__ out)
{
    extern __shared__ unsigned char smem_raw[];
    float*    sp     = (float*)smem_raw;                                  // F_
    unsigned* sk     = (unsigned*)(smem_raw + (size_t)F_ * 4);            // F_
    unsigned* hist   = (unsigned*)(smem_raw + (size_t)F_ * 8);            // 4096
    int*      selIdx = (int*)(smem_raw + (size_t)F_ * 8 + 4096 * 4);      // 256
    int*      eqIdx  = (int*)((char*)selIdx + 256 * 4);                   // 64

    __shared__ SelShared sh;
    __shared__ int   feats32[K1];
    __shared__ float w32[K1];
    __shared__ float uw[K2_];

    const int tid = threadIdx.x;
    const int b   = blockIdx.x;

    // load this row of project into smem
    const float* prow = g_project + (size_t)b * F_;
    for (int i = tid; i < F_; i += NTH) sp[i] = prow[i];

    // fuzz = std(project, ddof=1) * FUZZ_FACTOR(=1)
    const double S  = g_sum;
    const double SS = g_sumsq;
    const double N  = (double)B_ * (double)F_;
    const float fuzz = (float)sqrt((SS - S * S / N) / (N - 1.0));

    // ---- pass 1: top-32 of project ----
    __syncthreads();
    for (int i = tid; i < F_; i += NTH) sk[i] = fkey(sp[i]);
    __syncthreads();
    select_topk(sk, hist, selIdx, eqIdx, K1, &sh);
    for (int j = tid; j < K1; j += NTH) {
        feats32[j] = selIdx[j];
        w32[j]     = sp[selIdx[j]];
    }
    __syncthreads();

    // ---- pass 2: top-256 of fuzzed dead features ----
    const float* nrow = noise + (size_t)b * F_;
    for (int i = tid; i < F_; i += NTH)
        sk[i] = (last_usage[i] > DEAD_CUT) ? fkey(sp[i] + fuzz * nrow[i]) : 0u;
    __syncthreads();
    select_topk(sk, hist, selIdx, eqIdx, K2_, &sh);
    for (int j = tid; j < K2_; j += NTH) uw[j] = sp[selIdx[j]];   // weight = project value
    __syncthreads();

    // ---- reconstruction ----
    for (int d = tid; d < D_; d += NTH) {
        float a = bias[d];
#pragma unroll 8
        for (int k = 0; k < K1; k++)
            a += w32[k] * lookup[(size_t)feats32[k] * D_ + d];
        out[(size_t)b * D_ + d] = a;

        float a0 = 0.f, a1 = 0.f, a2 = 0.f, a3 = 0.f;
#pragma unroll 2
        for (int k = 0; k < K2_; k += 4) {
            a0 += uw[k + 0] * lookup[(size_t)selIdx[k + 0] * D_ + d];
            a1 += uw[k + 1] * lookup[(size_t)selIdx[k + 1] * D_ + d];
            a2 += uw[k + 2] * lookup[(size_t)selIdx[k + 2] * D_ + d];
            a3 += uw[k + 3] * lookup[(size_t)selIdx[k + 3] * D_ + d];
        }
        out[(size_t)B_ * D_ + (size_t)b * D_ + d] = (a0 + a1) + (a2 + a3);
    }
}

// ---------------------------------------------------------------------------
// Launch
// ---------------------------------------------------------------------------
extern "C" void kernel_launch(void* const* d_in, const int* in_sizes, int n_in,
                              void* d_out, int out_size)
{
    (void)in_sizes; (void)n_in; (void)out_size;
    const float* embed      = (const float*)d_in[0];
    const float* enc_bias   = (const float*)d_in[1];
    const float* enc_W      = (const float*)d_in[2];
    const float* lookup     = (const float*)d_in[3];
    const float* noise      = (const float*)d_in[4];
    const int*   last_usage = (const int*)  d_in[5];
    float* out = (float*)d_out;

    const size_t smem_bytes = (size_t)F_ * 8 + 4096 * 4 + 256 * 4 + 64 * 4; // 214272
    cudaFuncSetAttribute(row_kernel,
                         cudaFuncAttributeMaxDynamicSharedMemorySize,
                         (int)smem_bytes);

    zero_stats_kernel<<<1, 1>>>();
    gemm_kernel<<<dim3(F_ / BN, B_ / BM), 256>>>(embed, enc_bias, enc_W);
    row_kernel<<<B_, NTH, smem_bytes>>>(noise, last_usage, lookup, enc_bias, out);
}

// round 9
// speedup vs baseline: 1.0067x; 1.0067x over previous
#include <cuda_runtime.h>
#include <math.h>

#define B_   4096
#define D_   1024
#define F_   24576
#define K1   32      /* TOPK */
#define K2_  256     /* DEAD_TOPK */
#define DEAD_CUT 100000
#define NTH  512     /* threads in row kernel */

// ---------------------------------------------------------------------------
// Scratch (device globals: no cudaMalloc allowed)
// ---------------------------------------------------------------------------
__device__ float  g_project[(size_t)B_ * (size_t)F_];   // 402 MB
__device__ double g_sum;
__device__ double g_sumsq;

__global__ void zero_stats_kernel() {
    g_sum = 0.0;
    g_sumsq = 0.0;
}

// ---------------------------------------------------------------------------
// SGEMM: project[b,f] = sum_d (embed[b,d]-bias[d]) * W[f,d]
// 128x128 tile, BK=16, 256 threads, 8x8 micro-tile, double buffered.
// Two-level accumulation (per-tile partial -> main acc) to cut rounding error
// from ~8e-7 to ~2.8e-7: the dead-topk boundary flips scale linearly with it.
// Also accumulates global sum / sumsq of project for std().
// ---------------------------------------------------------------------------
#define BM 128
#define BN 128
#define BK 16

__global__ __launch_bounds__(256, 1)
void gemm_kernel(const float* __restrict__ embed,
                 const float* __restrict__ bias,
                 const float* __restrict__ W)
{
    __shared__ __align__(16) float As[2][BK][BM];
    __shared__ __align__(16) float Bs[2][BK][BN];

    const int tid  = threadIdx.x;
    const int row0 = blockIdx.y * BM;   // batch rows
    const int col0 = blockIdx.x * BN;   // feature cols

    // loader mapping: each thread loads 2 float4 for A and 2 for B per stage
    const int ar0 = tid >> 2;                 // rows 0..63
    const int ar1 = (tid + 256) >> 2;         // rows 64..127
    const int aq  = tid & 3;                  // which float4 of the 16-wide k slab

    const float* Ap0 = embed + (size_t)(row0 + ar0) * D_ + aq * 4;
    const float* Ap1 = embed + (size_t)(row0 + ar1) * D_ + aq * 4;
    const float* Bp0 = W     + (size_t)(col0 + ar0) * D_ + aq * 4;
    const float* Bp1 = W     + (size_t)(col0 + ar1) * D_ + aq * 4;

    float acc[8][8];
#pragma unroll
    for (int i = 0; i < 8; i++)
#pragma unroll
        for (int j = 0; j < 8; j++) acc[i][j] = 0.0f;

    float4 a0, a1, b0, b1, bb;

    // preload tile 0
    a0 = *(const float4*)(Ap0);
    a1 = *(const float4*)(Ap1);
    b0 = *(const float4*)(Bp0);
    b1 = *(const float4*)(Bp1);
    bb = *(const float4*)(bias + aq * 4);

    int buf = 0;
    {
        const int kc = aq * 4;
        As[0][kc+0][ar0] = a0.x - bb.x;  As[0][kc+1][ar0] = a0.y - bb.y;
        As[0][kc+2][ar0] = a0.z - bb.z;  As[0][kc+3][ar0] = a0.w - bb.w;
        As[0][kc+0][ar1] = a1.x - bb.x;  As[0][kc+1][ar1] = a1.y - bb.y;
        As[0][kc+2][ar1] = a1.z - bb.z;  As[0][kc+3][ar1] = a1.w - bb.w;
        Bs[0][kc+0][ar0] = b0.x;  Bs[0][kc+1][ar0] = b0.y;
        Bs[0][kc+2][ar0] = b0.z;  Bs[0][kc+3][ar0] = b0.w;
        Bs[0][kc+0][ar1] = b1.x;  Bs[0][kc+1][ar1] = b1.y;
        Bs[0][kc+2][ar1] = b1.z;  Bs[0][kc+3][ar1] = b1.w;
    }
    __syncthreads();

    const int ty = tid >> 4;   // 0..15
    const int tx = tid & 15;   // 0..15
    const int NT = D_ / BK;    // 64

    for (int t = 0; t < NT; t++) {
        if (t + 1 < NT) {
            const int k0 = (t + 1) * BK;
            a0 = *(const float4*)(Ap0 + k0);
            a1 = *(const float4*)(Ap1 + k0);
            b0 = *(const float4*)(Bp0 + k0);
            b1 = *(const float4*)(Bp1 + k0);
            bb = *(const float4*)(bias + k0 + aq * 4);
        }
        // per-tile partial sums (fresh registers -> short rounding chains)
        float ts[8][8];
#pragma unroll
        for (int i = 0; i < 8; i++)
#pragma unroll
            for (int j = 0; j < 8; j++) ts[i][j] = 0.0f;
#pragma unroll
        for (int kk = 0; kk < BK; kk++) {
            float af[8], bf[8];
            *(float4*)&af[0] = *(const float4*)&As[buf][kk][ty * 8];
            *(float4*)&af[4] = *(const float4*)&As[buf][kk][ty * 8 + 4];
            *(float4*)&bf[0] = *(const float4*)&Bs[buf][kk][tx * 8];
            *(float4*)&bf[4] = *(const float4*)&Bs[buf][kk][tx * 8 + 4];
#pragma unroll
            for (int i = 0; i < 8; i++)
#pragma unroll
                for (int j = 0; j < 8; j++)
                    ts[i][j] += af[i] * bf[j];
        }
#pragma unroll
        for (int i = 0; i < 8; i++)
#pragma unroll
            for (int j = 0; j < 8; j++)
                acc[i][j] += ts[i][j];

        if (t + 1 < NT) {
            const int nb = buf ^ 1;
            const int kc = aq * 4;
            As[nb][kc+0][ar0] = a0.x - bb.x;  As[nb][kc+1][ar0] = a0.y - bb.y;
            As[nb][kc+2][ar0] = a0.z - bb.z;  As[nb][kc+3][ar0] = a0.w - bb.w;
            As[nb][kc+0][ar1] = a1.x - bb.x;  As[nb][kc+1][ar1] = a1.y - bb.y;
            As[nb][kc+2][ar1] = a1.z - bb.z;  As[nb][kc+3][ar1] = a1.w - bb.w;
            Bs[nb][kc+0][ar0] = b0.x;  Bs[nb][kc+1][ar0] = b0.y;
            Bs[nb][kc+2][ar0] = b0.z;  Bs[nb][kc+3][ar0] = b0.w;
            Bs[nb][kc+0][ar1] = b1.x;  Bs[nb][kc+1][ar1] = b1.y;
            Bs[nb][kc+2][ar1] = b1.z;  Bs[nb][kc+3][ar1] = b1.w;
            __syncthreads();
            buf = nb;
        }
    }

    // write C + accumulate stats
    float s = 0.0f, ss = 0.0f;
#pragma unroll
    for (int i = 0; i < 8; i++) {
        const size_t base = (size_t)(row0 + ty * 8 + i) * F_ + (col0 + tx * 8);
        float4 c0 = make_float4(acc[i][0], acc[i][1], acc[i][2], acc[i][3]);
        float4 c1 = make_float4(acc[i][4], acc[i][5], acc[i][6], acc[i][7]);
        *(float4*)&g_project[base]     = c0;
        *(float4*)&g_project[base + 4] = c1;
#pragma unroll
        for (int j = 0; j < 8; j++) { float v = acc[i][j]; s += v; ss += v * v; }
    }
#pragma unroll
    for (int o = 16; o > 0; o >>= 1) {
        s  += __shfl_down_sync(0xffffffffu, s,  o);
        ss += __shfl_down_sync(0xffffffffu, ss, o);
    }
    __shared__ double wsum[8], wss[8];
    const int w = tid >> 5, l = tid & 31;
    if (l == 0) { wsum[w] = (double)s; wss[w] = (double)ss; }
    __syncthreads();
    if (tid == 0) {
        double S = 0.0, SS = 0.0;
        for (int i = 0; i < 8; i++) { S += wsum[i]; SS += wss[i]; }
        atomicAdd(&g_sum, S);
        atomicAdd(&g_sumsq, SS);
    }
}

// ---------------------------------------------------------------------------
// Per-row top-k (exact radix select on monotone float keys) + reconstruction
// ---------------------------------------------------------------------------
__device__ __forceinline__ unsigned fkey(float v) {
    unsigned u = __float_as_uint(v);
    return (u & 0x80000000u) ? ~u : (u | 0x80000000u);
}

struct SelShared { int T; int nsel; int neq; };

__device__ void suffix_scan(unsigned* h, int NB) {
    const int tid = threadIdx.x;
    for (int off = 1; off < NB; off <<= 1) {
        unsigned v[8];
        int c = 0;
        for (int idx = tid; idx < NB; idx += NTH) {
            const int srcIdx = idx + off;
            v[c++] = (srcIdx < NB) ? h[srcIdx] : 0u;
        }
        __syncthreads();
        c = 0;
        for (int idx = tid; idx < NB; idx += NTH) h[idx] += v[c++];
        __syncthreads();
    }
}

__device__ int find_T(unsigned* h, int NB, unsigned K, int* sT) {
    const int tid = threadIdx.x;
    for (int idx = tid; idx < NB; idx += NTH)
        if (h[idx] >= K && (idx == NB - 1 || h[idx + 1] < K)) *sT = idx;
    __syncthreads();
    return *sT;
}

// exact top-K of keys sk[0..F_) -> indices in selIdx[0..K)
__device__ void select_topk(const unsigned* sk, unsigned* hist,
                            int* selIdx, int* eqIdx, int K, SelShared* sh)
{
    const int tid = threadIdx.x;
    const unsigned Ku = (unsigned)K;

    // round 1: key bits [31:20]
    for (int i = tid; i < 4096; i += NTH) hist[i] = 0u;
    __syncthreads();
    for (int i = tid; i < F_; i += NTH) atomicAdd(&hist[sk[i] >> 20], 1u);
    __syncthreads();
    suffix_scan(hist, 4096);
    const int T1 = find_T(hist, 4096, Ku, &sh->T);
    const unsigned nA1 = (T1 < 4095) ? hist[T1 + 1] : 0u;
    unsigned Kr = Ku - nA1;
    __syncthreads();

    // round 2: bits [19:8], restricted to top12 == T1
    for (int i = tid; i < 4096; i += NTH) hist[i] = 0u;
    __syncthreads();
    for (int i = tid; i < F_; i += NTH) {
        const unsigned k = sk[i];
        if ((int)(k >> 20) == T1) atomicAdd(&hist[(k >> 8) & 0xFFFu], 1u);
    }
    __syncthreads();
    suffix_scan(hist, 4096);
    const int T2 = find_T(hist, 4096, Kr, &sh->T);
    const unsigned nA2 = (T2 < 4095) ? hist[T2 + 1] : 0u;
    Kr -= nA2;
    __syncthreads();

    // round 3: bits [7:0], restricted to top24 == (T1<<12)|T2
    const unsigned pre24 = ((unsigned)T1 << 12) | (unsigned)T2;
    for (int i = tid; i < 256; i += NTH) hist[i] = 0u;
    __syncthreads();
    for (int i = tid; i < F_; i += NTH) {
        const unsigned k = sk[i];
        if ((k >> 8) == pre24) atomicAdd(&hist[k & 0xFFu], 1u);
    }
    __syncthreads();
    suffix_scan(hist, 256);
    const int T3 = find_T(hist, 256, Kr, &sh->T);
    const unsigned nA3 = (T3 < 255) ? hist[T3 + 1] : 0u;
    const int needEq = (int)(Kr - nA3);
    const unsigned kth = (pre24 << 8) | (unsigned)T3;
    __syncthreads();

    // collect: all keys > kth, plus needEq keys == kth (lowest index first)
    if (tid == 0) { sh->nsel = 0; sh->neq = 0; }
    __syncthreads();
    for (int i = tid; i < F_; i += NTH) {
        const unsigned k = sk[i];
        if (k > kth) {
            const int p = atomicAdd(&sh->nsel, 1);
            selIdx[p] = i;
        } else if (k == kth) {
            const int p = atomicAdd(&sh->neq, 1);
            if (p < 64) eqIdx[p] = i;
        }
    }
    __syncthreads();
    if (tid == 0) {
        int m = sh->neq; if (m > 64) m = 64;
        for (int a = 1; a < m; a++) {           // tiny insertion sort by index
            int v = eqIdx[a]; int c = a - 1;
            while (c >= 0 && eqIdx[c] > v) { eqIdx[c + 1] = eqIdx[c]; c--; }
            eqIdx[c + 1] = v;
        }
        const int base = sh->nsel;
        for (int a = 0; a < needEq; a++)
            selIdx[base + a] = (a < m) ? eqIdx[a] : eqIdx[0];
    }
    __syncthreads();
}

__global__ __launch_bounds__(NTH)
void row_kernel(const float* __restrict__ noise,
                const int*   __restrict__ last_usage,
                const float* __restrict__ lookup,
                const float* __restrict__ bias,
                float* __restrict__ out)
{
    extern __shared__ unsigned char smem_raw[];
    float*    sp     = (float*)smem_raw;                                  // F_
    unsigned* sk     = (unsigned*)(smem_raw + (size_t)F_ * 4);            // F_
    unsigned* hist   = (unsigned*)(smem_raw + (size_t)F_ * 8);            // 4096
    int*      selIdx = (int*)(smem_raw + (size_t)F_ * 8 + 4096 * 4);      // 256
    int*      eqIdx  = (int*)((char*)selIdx + 256 * 4);                   // 64

    __shared__ SelShared sh;
    __shared__ int   feats32[K1];
    __shared__ float w32[K1];
    __shared__ float uw[K2_];

    const int tid = threadIdx.x;
    const int b   = blockIdx.x;

    // load this row of project into smem
    const float* prow = g_project + (size_t)b * F_;
    for (int i = tid; i < F_; i += NTH) sp[i] = prow[i];

    // fuzz = std(project, ddof=1) * FUZZ_FACTOR(=1)
    const double S  = g_sum;
    const double SS = g_sumsq;
    const double N  = (double)B_ * (double)F_;
    const float fuzz = (float)sqrt((SS - S * S / N) / (N - 1.0));

    // ---- pass 1: top-32 of project ----
    __syncthreads();
    for (int i = tid; i < F_; i += NTH) sk[i] = fkey(sp[i]);
    __syncthreads();
    select_topk(sk, hist, selIdx, eqIdx, K1, &sh);
    for (int j = tid; j < K1; j += NTH) {
        feats32[j] = selIdx[j];
        w32[j]     = sp[selIdx[j]];
    }
    __syncthreads();

    // ---- pass 2: top-256 of fuzzed dead features ----
    const float* nrow = noise + (size_t)b * F_;
    for (int i = tid; i < F_; i += NTH)
        sk[i] = (last_usage[i] > DEAD_CUT) ? fkey(sp[i] + fuzz * nrow[i]) : 0u;
    __syncthreads();
    select_topk(sk, hist, selIdx, eqIdx, K2_, &sh);
    for (int j = tid; j < K2_; j += NTH) uw[j] = sp[selIdx[j]];   // weight = project value
    __syncthreads();

    // ---- reconstruction ----
    for (int d = tid; d < D_; d += NTH) {
        float a = bias[d];
#pragma unroll 8
        for (int k = 0; k < K1; k++)
            a += w32[k] * lookup[(size_t)feats32[k] * D_ + d];
        out[(size_t)b * D_ + d] = a;

        float a0 = 0.f, a1 = 0.f, a2 = 0.f, a3 = 0.f;
#pragma unroll 2
        for (int k = 0; k < K2_; k += 4) {
            a0 += uw[k + 0] * lookup[(size_t)selIdx[k + 0] * D_ + d];
            a1 += uw[k + 1] * lookup[(size_t)selIdx[k + 1] * D_ + d];
            a2 += uw[k + 2] * lookup[(size_t)selIdx[k + 2] * D_ + d];
            a3 += uw[k + 3] * lookup[(size_t)selIdx[k + 3] * D_ + d];
        }
        out[(size_t)B_ * D_ + (size_t)b * D_ + d] = (a0 + a1) + (a2 + a3);
    }
}

// ---------------------------------------------------------------------------
// Launch
// ---------------------------------------------------------------------------
extern "C" void kernel_launch(void* const* d_in, const int* in_sizes, int n_in,
                              void* d_out, int out_size)
{
    (void)in_sizes; (void)n_in; (void)out_size;
    const float* embed      = (const float*)d_in[0];
    const float* enc_bias   = (const float*)d_in[1];
    const float* enc_W      = (const float*)d_in[2];
    const float* lookup     = (const float*)d_in[3];
    const float* noise      = (const float*)d_in[4];
    const int*   last_usage = (const int*)  d_in[5];
    float* out = (float*)d_out;

    const size_t smem_bytes = (size_t)F_ * 8 + 4096 * 4 + 256 * 4 + 64 * 4; // 214272
    cudaFuncSetAttribute(row_kernel,
                         cudaFuncAttributeMaxDynamicSharedMemorySize,
                         (int)smem_bytes);

    zero_stats_kernel<<<1, 1>>>();
    gemm_kernel<<<dim3(F_ / BN, B_ / BM), 256>>>(embed, enc_bias, enc_W);
    row_kernel<<<B_, NTH, smem_bytes>>>(noise, last_usage, lookup, enc_bias, out);
}